// round 1
// baseline (speedup 1.0000x reference)
#include <cuda_runtime.h>
#include <cstdint>

#define N_NODES 100000
#define H1 4
#define F1 16
#define C1 64          // H1*F1
#define FIN 128
#define C2 16
#define NEG 0.2f

// ---------------- scratch (static device arrays; no allocation) -------------
__device__ float g_h1[N_NODES * C1];
__device__ float g_as1[N_NODES * H1];
__device__ float g_ad1[N_NODES * H1];
__device__ float g_z1[N_NODES * H1];
__device__ float g_acc1[N_NODES * C1];
__device__ float g_h2[N_NODES * C2];
__device__ float g_as2[N_NODES];
__device__ float g_ad2[N_NODES];
__device__ float g_z2[N_NODES];
__device__ float g_acc2[N_NODES * C2];

__device__ __forceinline__ float lrelu(float v) { return v > 0.f ? v : NEG * v; }

__device__ __forceinline__ void red_add_v4(float* p, float a, float b, float c, float d) {
    asm volatile("red.global.add.v4.f32 [%0], {%1,%2,%3,%4};"
                 :: "l"(p), "f"(a), "f"(b), "f"(c), "f"(d) : "memory");
}

// ---------------- kernel 1: h1 = x @ W1^T, alpha dots, z1 self-init ---------
__global__ __launch_bounds__(128) void k_gemm1(const float* __restrict__ x,
                                               const float* __restrict__ W1,
                                               const float* __restrict__ asrc,
                                               const float* __restrict__ adst) {
    __shared__ float sW[C1 * FIN];  // 32 KB
    for (int i = threadIdx.x; i < C1 * FIN; i += 128) sW[i] = W1[i];
    __syncthreads();

    int n = blockIdx.x * 128 + threadIdx.x;
    if (n >= N_NODES) return;

    float acc[C1];
#pragma unroll
    for (int j = 0; j < C1; j++) acc[j] = 0.f;

    const float4* xr = (const float4*)(x + (size_t)n * FIN);
#pragma unroll 4
    for (int kk = 0; kk < FIN / 4; kk++) {
        float4 xv = __ldg(xr + kk);
#pragma unroll
        for (int j = 0; j < C1; j++) {
            float4 wv = *(const float4*)(sW + j * FIN + kk * 4);
            acc[j] += xv.x * wv.x + xv.y * wv.y + xv.z * wv.z + xv.w * wv.w;
        }
    }

    float as[H1], ad[H1];
#pragma unroll
    for (int h = 0; h < H1; h++) {
        float s = 0.f, d = 0.f;
#pragma unroll
        for (int f = 0; f < F1; f++) {
            float hv = acc[h * F1 + f];
            s += hv * __ldg(asrc + h * F1 + f);
            d += hv * __ldg(adst + h * F1 + f);
        }
        as[h] = s; ad[h] = d;
    }

    float4* hout = (float4*)(g_h1 + (size_t)n * C1);
#pragma unroll
    for (int j = 0; j < C1 / 4; j++)
        hout[j] = make_float4(acc[4 * j], acc[4 * j + 1], acc[4 * j + 2], acc[4 * j + 3]);

    *(float4*)(g_as1 + n * 4) = make_float4(as[0], as[1], as[2], as[3]);
    *(float4*)(g_ad1 + n * 4) = make_float4(ad[0], ad[1], ad[2], ad[3]);
    // z1 initialized with self-loop contribution (softmax shift skipped: shift-invariant)
    *(float4*)(g_z1 + n * 4) = make_float4(__expf(lrelu(as[0] + ad[0])),
                                           __expf(lrelu(as[1] + ad[1])),
                                           __expf(lrelu(as[2] + ad[2])),
                                           __expf(lrelu(as[3] + ad[3])));
}

// ---------------- kernel 2: z1 accumulation over edges ----------------------
__global__ void k_edge_z1(const int* __restrict__ src, const int* __restrict__ dst, int E) {
    int e = blockIdx.x * blockDim.x + threadIdx.x;
    if (e >= E) return;
    int s = __ldg(src + e), d = __ldg(dst + e);
    float4 a = *(const float4*)(g_as1 + s * 4);
    float4 b = *(const float4*)(g_ad1 + d * 4);
    red_add_v4(g_z1 + d * 4,
               __expf(lrelu(a.x + b.x)), __expf(lrelu(a.y + b.y)),
               __expf(lrelu(a.z + b.z)), __expf(lrelu(a.w + b.w)));
}

// ---------------- kernel 3: layer-1 message scatter -------------------------
__global__ void k_edge_msg1(const int* __restrict__ src, const int* __restrict__ dst, int E) {
    int e = blockIdx.x * blockDim.x + threadIdx.x;
    if (e >= E) return;
    int s = __ldg(src + e), d = __ldg(dst + e);
    float4 a = *(const float4*)(g_as1 + s * 4);
    float4 b = *(const float4*)(g_ad1 + d * 4);
    float4 z = *(const float4*)(g_z1 + d * 4);
    float w[H1];
    w[0] = __expf(lrelu(a.x + b.x)) / z.x;
    w[1] = __expf(lrelu(a.y + b.y)) / z.y;
    w[2] = __expf(lrelu(a.z + b.z)) / z.z;
    w[3] = __expf(lrelu(a.w + b.w)) / z.w;
    const float4* hs = (const float4*)(g_h1 + (size_t)s * C1);
    float* od = g_acc1 + (size_t)d * C1;
#pragma unroll
    for (int i = 0; i < C1 / 4; i++) {
        float4 hv = __ldg(hs + i);
        float ww = w[i >> 2];
        red_add_v4(od + i * 4, hv.x * ww, hv.y * ww, hv.z * ww, hv.w * ww);
    }
}

// ---------------- kernel 4: finish layer 1, layer-2 linear + alphas ---------
__global__ __launch_bounds__(128) void k_node2(const float* __restrict__ b1,
                                               const float* __restrict__ W2,
                                               const float* __restrict__ asrc2,
                                               const float* __restrict__ adst2) {
    __shared__ float sW[C2 * C1];  // 4 KB
    for (int i = threadIdx.x; i < C2 * C1; i += 128) sW[i] = W2[i];
    __syncthreads();

    int n = blockIdx.x * 128 + threadIdx.x;
    if (n >= N_NODES) return;

    float4 a = *(const float4*)(g_as1 + n * 4);
    float4 b = *(const float4*)(g_ad1 + n * 4);
    float4 z = *(const float4*)(g_z1 + n * 4);
    float sw[H1];
    sw[0] = __expf(lrelu(a.x + b.x)) / z.x;
    sw[1] = __expf(lrelu(a.y + b.y)) / z.y;
    sw[2] = __expf(lrelu(a.z + b.z)) / z.z;
    sw[3] = __expf(lrelu(a.w + b.w)) / z.w;

    float v[C1];
    const float4* ac = (const float4*)(g_acc1 + (size_t)n * C1);
    const float4* hh = (const float4*)(g_h1 + (size_t)n * C1);
#pragma unroll
    for (int i = 0; i < C1 / 4; i++) {
        float4 av = ac[i];
        float4 hv = hh[i];
        float s = sw[i >> 2];
        float bx = __ldg(b1 + 4 * i), by = __ldg(b1 + 4 * i + 1),
              bz = __ldg(b1 + 4 * i + 2), bw = __ldg(b1 + 4 * i + 3);
        v[4 * i + 0] = fmaxf(av.x + s * hv.x + bx, 0.f);
        v[4 * i + 1] = fmaxf(av.y + s * hv.y + by, 0.f);
        v[4 * i + 2] = fmaxf(av.z + s * hv.z + bz, 0.f);
        v[4 * i + 3] = fmaxf(av.w + s * hv.w + bw, 0.f);
    }

    float h2[C2];
#pragma unroll
    for (int j = 0; j < C2; j++) h2[j] = 0.f;
#pragma unroll
    for (int kk = 0; kk < C1 / 4; kk++) {
#pragma unroll
        for (int j = 0; j < C2; j++) {
            float4 wv = *(const float4*)(sW + j * C1 + kk * 4);
            h2[j] += v[4 * kk] * wv.x + v[4 * kk + 1] * wv.y +
                     v[4 * kk + 2] * wv.z + v[4 * kk + 3] * wv.w;
        }
    }

    float s2 = 0.f, d2 = 0.f;
#pragma unroll
    for (int j = 0; j < C2; j++) {
        s2 += h2[j] * __ldg(asrc2 + j);
        d2 += h2[j] * __ldg(adst2 + j);
    }

    float4* ho = (float4*)(g_h2 + (size_t)n * C2);
#pragma unroll
    for (int j = 0; j < C2 / 4; j++)
        ho[j] = make_float4(h2[4 * j], h2[4 * j + 1], h2[4 * j + 2], h2[4 * j + 3]);
    g_as2[n] = s2;
    g_ad2[n] = d2;
    g_z2[n] = __expf(lrelu(s2 + d2));  // self-loop init
}

// ---------------- kernel 5: z2 accumulation ---------------------------------
__global__ void k_edge_z2(const int* __restrict__ src, const int* __restrict__ dst, int E) {
    int e = blockIdx.x * blockDim.x + threadIdx.x;
    if (e >= E) return;
    int s = __ldg(src + e), d = __ldg(dst + e);
    float w = __expf(lrelu(g_as2[s] + g_ad2[d]));
    atomicAdd(&g_z2[d], w);
}

// ---------------- kernel 6: layer-2 message scatter -------------------------
__global__ void k_edge_msg2(const int* __restrict__ src, const int* __restrict__ dst, int E) {
    int e = blockIdx.x * blockDim.x + threadIdx.x;
    if (e >= E) return;
    int s = __ldg(src + e), d = __ldg(dst + e);
    float w = __expf(lrelu(g_as2[s] + g_ad2[d])) / g_z2[d];
    const float4* hs = (const float4*)(g_h2 + (size_t)s * C2);
    float* od = g_acc2 + (size_t)d * C2;
#pragma unroll
    for (int i = 0; i < C2 / 4; i++) {
        float4 hv = __ldg(hs + i);
        red_add_v4(od + i * 4, hv.x * w, hv.y * w, hv.z * w, hv.w * w);
    }
}

// ---------------- kernel 7: self msg + b2 + log_softmax ---------------------
__global__ void k_final(const float* __restrict__ b2, float* __restrict__ out) {
    int n = blockIdx.x * blockDim.x + threadIdx.x;
    if (n >= N_NODES) return;
    float sw = __expf(lrelu(g_as2[n] + g_ad2[n])) / g_z2[n];
    float v[C2];
    const float4* ac = (const float4*)(g_acc2 + (size_t)n * C2);
    const float4* hh = (const float4*)(g_h2 + (size_t)n * C2);
#pragma unroll
    for (int i = 0; i < C2 / 4; i++) {
        float4 av = ac[i];
        float4 hv = hh[i];
        v[4 * i + 0] = av.x + sw * hv.x + __ldg(b2 + 4 * i + 0);
        v[4 * i + 1] = av.y + sw * hv.y + __ldg(b2 + 4 * i + 1);
        v[4 * i + 2] = av.z + sw * hv.z + __ldg(b2 + 4 * i + 2);
        v[4 * i + 3] = av.w + sw * hv.w + __ldg(b2 + 4 * i + 3);
    }
    float m = v[0];
#pragma unroll
    for (int i = 1; i < C2; i++) m = fmaxf(m, v[i]);
    float s = 0.f;
#pragma unroll
    for (int i = 0; i < C2; i++) s += expf(v[i] - m);
    float l = m + logf(s);
    float4* o = (float4*)(out + (size_t)n * C2);
#pragma unroll
    for (int i = 0; i < C2 / 4; i++)
        o[i] = make_float4(v[4 * i] - l, v[4 * i + 1] - l, v[4 * i + 2] - l, v[4 * i + 3] - l);
}

// ---------------- launch ----------------------------------------------------
extern "C" void kernel_launch(void* const* d_in, const int* in_sizes, int n_in,
                              void* d_out, int out_size) {
    const float* x     = (const float*)d_in[0];
    const int*   ei    = (const int*)d_in[1];
    const float* W1    = (const float*)d_in[2];
    const float* as1   = (const float*)d_in[3];
    const float* ad1   = (const float*)d_in[4];
    const float* b1    = (const float*)d_in[5];
    const float* W2    = (const float*)d_in[6];
    const float* as2   = (const float*)d_in[7];
    const float* ad2   = (const float*)d_in[8];
    const float* b2    = (const float*)d_in[9];
    float* out = (float*)d_out;

    int E = in_sizes[1] / 2;           // edge_index is [2, E] int32
    const int* src = ei;
    const int* dst = ei + E;

    void *acc1p, *acc2p;
    cudaGetSymbolAddress(&acc1p, g_acc1);
    cudaGetSymbolAddress(&acc2p, g_acc2);
    cudaMemsetAsync(acc1p, 0, sizeof(float) * (size_t)N_NODES * C1);
    cudaMemsetAsync(acc2p, 0, sizeof(float) * (size_t)N_NODES * C2);

    int nb = (N_NODES + 127) / 128;
    int eb = (E + 255) / 256;

    k_gemm1<<<nb, 128>>>(x, W1, as1, ad1);
    k_edge_z1<<<eb, 256>>>(src, dst, E);
    k_edge_msg1<<<eb, 256>>>(src, dst, E);
    k_node2<<<nb, 128>>>(b1, W2, as2, ad2);
    k_edge_z2<<<eb, 256>>>(src, dst, E);
    k_edge_msg2<<<eb, 256>>>(src, dst, E);
    k_final<<<(N_NODES + 255) / 256, 256>>>(b2, out);
}

// round 2
// speedup vs baseline: 1.0041x; 1.0041x over previous
#include <cuda_runtime.h>
#include <cstdint>

#define N_NODES 100000
#define H1 4
#define F1 16
#define C1 64          // H1*F1
#define FIN 128
#define C2 16
#define NEG 0.2f

// ---------------- scratch (static device arrays; no allocation) -------------
__device__ float g_h1[N_NODES * C1];
__device__ float g_as1[N_NODES * H1];
__device__ float g_ad1[N_NODES * H1];
__device__ float g_z1[N_NODES * H1];
__device__ float g_acc1[N_NODES * C1];
__device__ float g_h2[N_NODES * C2];
__device__ float g_as2[N_NODES];
__device__ float g_ad2[N_NODES];
__device__ float g_z2[N_NODES];
__device__ float g_acc2[N_NODES * C2];

__device__ __forceinline__ float lrelu(float v) { return v > 0.f ? v : NEG * v; }

__device__ __forceinline__ void red_add_v4(float* p, float a, float b, float c, float d) {
    asm volatile("red.global.add.v4.f32 [%0], {%1,%2,%3,%4};"
                 :: "l"(p), "f"(a), "f"(b), "f"(c), "f"(d) : "memory");
}

// ---------------- kernel 1: h1 = x @ W1^T, alpha dots, z1 self-init ---------
__global__ __launch_bounds__(128) void k_gemm1(const float* __restrict__ x,
                                               const float* __restrict__ W1,
                                               const float* __restrict__ asrc,
                                               const float* __restrict__ adst) {
    __shared__ float sW[C1 * FIN];  // 32 KB
    for (int i = threadIdx.x; i < C1 * FIN; i += 128) sW[i] = W1[i];
    __syncthreads();

    int n = blockIdx.x * 128 + threadIdx.x;
    if (n >= N_NODES) return;

    float acc[C1];
#pragma unroll
    for (int j = 0; j < C1; j++) acc[j] = 0.f;

    const float4* xr = (const float4*)(x + (size_t)n * FIN);
#pragma unroll 4
    for (int kk = 0; kk < FIN / 4; kk++) {
        float4 xv = __ldg(xr + kk);
#pragma unroll
        for (int j = 0; j < C1; j++) {
            float4 wv = *(const float4*)(sW + j * FIN + kk * 4);
            acc[j] += xv.x * wv.x + xv.y * wv.y + xv.z * wv.z + xv.w * wv.w;
        }
    }

    float as[H1], ad[H1];
#pragma unroll
    for (int h = 0; h < H1; h++) {
        float s = 0.f, d = 0.f;
#pragma unroll
        for (int f = 0; f < F1; f++) {
            float hv = acc[h * F1 + f];
            s += hv * __ldg(asrc + h * F1 + f);
            d += hv * __ldg(adst + h * F1 + f);
        }
        as[h] = s; ad[h] = d;
    }

    float4* hout = (float4*)(g_h1 + (size_t)n * C1);
#pragma unroll
    for (int j = 0; j < C1 / 4; j++)
        hout[j] = make_float4(acc[4 * j], acc[4 * j + 1], acc[4 * j + 2], acc[4 * j + 3]);

    *(float4*)(g_as1 + n * 4) = make_float4(as[0], as[1], as[2], as[3]);
    *(float4*)(g_ad1 + n * 4) = make_float4(ad[0], ad[1], ad[2], ad[3]);
    // z1 initialized with self-loop contribution (softmax shift skipped: shift-invariant)
    *(float4*)(g_z1 + n * 4) = make_float4(__expf(lrelu(as[0] + ad[0])),
                                           __expf(lrelu(as[1] + ad[1])),
                                           __expf(lrelu(as[2] + ad[2])),
                                           __expf(lrelu(as[3] + ad[3])));
}

// ---------------- kernel 2: z1 accumulation over edges ----------------------
__global__ void k_edge_z1(const int* __restrict__ src, const int* __restrict__ dst, int E) {
    int e = blockIdx.x * blockDim.x + threadIdx.x;
    if (e >= E) return;
    int s = __ldg(src + e), d = __ldg(dst + e);
    float4 a = *(const float4*)(g_as1 + s * 4);
    float4 b = *(const float4*)(g_ad1 + d * 4);
    red_add_v4(g_z1 + d * 4,
               __expf(lrelu(a.x + b.x)), __expf(lrelu(a.y + b.y)),
               __expf(lrelu(a.z + b.z)), __expf(lrelu(a.w + b.w)));
}

// ---------------- kernel 3: layer-1 message scatter -------------------------
__global__ void k_edge_msg1(const int* __restrict__ src, const int* __restrict__ dst, int E) {
    int e = blockIdx.x * blockDim.x + threadIdx.x;
    if (e >= E) return;
    int s = __ldg(src + e), d = __ldg(dst + e);
    float4 a = *(const float4*)(g_as1 + s * 4);
    float4 b = *(const float4*)(g_ad1 + d * 4);
    float4 z = *(const float4*)(g_z1 + d * 4);
    float w[H1];
    w[0] = __expf(lrelu(a.x + b.x)) / z.x;
    w[1] = __expf(lrelu(a.y + b.y)) / z.y;
    w[2] = __expf(lrelu(a.z + b.z)) / z.z;
    w[3] = __expf(lrelu(a.w + b.w)) / z.w;
    const float4* hs = (const float4*)(g_h1 + (size_t)s * C1);
    float* od = g_acc1 + (size_t)d * C1;
#pragma unroll
    for (int i = 0; i < C1 / 4; i++) {
        float4 hv = __ldg(hs + i);
        float ww = w[i >> 2];
        red_add_v4(od + i * 4, hv.x * ww, hv.y * ww, hv.z * ww, hv.w * ww);
    }
}

// ---------------- kernel 4: finish layer 1, layer-2 linear + alphas ---------
__global__ __launch_bounds__(128) void k_node2(const float* __restrict__ b1,
                                               const float* __restrict__ W2,
                                               const float* __restrict__ asrc2,
                                               const float* __restrict__ adst2) {
    __shared__ float sW[C2 * C1];  // 4 KB
    for (int i = threadIdx.x; i < C2 * C1; i += 128) sW[i] = W2[i];
    __syncthreads();

    int n = blockIdx.x * 128 + threadIdx.x;
    if (n >= N_NODES) return;

    float4 a = *(const float4*)(g_as1 + n * 4);
    float4 b = *(const float4*)(g_ad1 + n * 4);
    float4 z = *(const float4*)(g_z1 + n * 4);
    float sw[H1];
    sw[0] = __expf(lrelu(a.x + b.x)) / z.x;
    sw[1] = __expf(lrelu(a.y + b.y)) / z.y;
    sw[2] = __expf(lrelu(a.z + b.z)) / z.z;
    sw[3] = __expf(lrelu(a.w + b.w)) / z.w;

    float v[C1];
    const float4* ac = (const float4*)(g_acc1 + (size_t)n * C1);
    const float4* hh = (const float4*)(g_h1 + (size_t)n * C1);
#pragma unroll
    for (int i = 0; i < C1 / 4; i++) {
        float4 av = ac[i];
        float4 hv = hh[i];
        float s = sw[i >> 2];
        float bx = __ldg(b1 + 4 * i), by = __ldg(b1 + 4 * i + 1),
              bz = __ldg(b1 + 4 * i + 2), bw = __ldg(b1 + 4 * i + 3);
        v[4 * i + 0] = fmaxf(av.x + s * hv.x + bx, 0.f);
        v[4 * i + 1] = fmaxf(av.y + s * hv.y + by, 0.f);
        v[4 * i + 2] = fmaxf(av.z + s * hv.z + bz, 0.f);
        v[4 * i + 3] = fmaxf(av.w + s * hv.w + bw, 0.f);
    }

    float h2[C2];
#pragma unroll
    for (int j = 0; j < C2; j++) h2[j] = 0.f;
#pragma unroll
    for (int kk = 0; kk < C1 / 4; kk++) {
#pragma unroll
        for (int j = 0; j < C2; j++) {
            float4 wv = *(const float4*)(sW + j * C1 + kk * 4);
            h2[j] += v[4 * kk] * wv.x + v[4 * kk + 1] * wv.y +
                     v[4 * kk + 2] * wv.z + v[4 * kk + 3] * wv.w;
        }
    }

    float s2 = 0.f, d2 = 0.f;
#pragma unroll
    for (int j = 0; j < C2; j++) {
        s2 += h2[j] * __ldg(asrc2 + j);
        d2 += h2[j] * __ldg(adst2 + j);
    }

    float4* ho = (float4*)(g_h2 + (size_t)n * C2);
#pragma unroll
    for (int j = 0; j < C2 / 4; j++)
        ho[j] = make_float4(h2[4 * j], h2[4 * j + 1], h2[4 * j + 2], h2[4 * j + 3]);
    g_as2[n] = s2;
    g_ad2[n] = d2;
    g_z2[n] = __expf(lrelu(s2 + d2));  // self-loop init
}

// ---------------- kernel 5: z2 accumulation ---------------------------------
__global__ void k_edge_z2(const int* __restrict__ src, const int* __restrict__ dst, int E) {
    int e = blockIdx.x * blockDim.x + threadIdx.x;
    if (e >= E) return;
    int s = __ldg(src + e), d = __ldg(dst + e);
    float w = __expf(lrelu(g_as2[s] + g_ad2[d]));
    atomicAdd(&g_z2[d], w);
}

// ---------------- kernel 6: layer-2 message scatter -------------------------
__global__ void k_edge_msg2(const int* __restrict__ src, const int* __restrict__ dst, int E) {
    int e = blockIdx.x * blockDim.x + threadIdx.x;
    if (e >= E) return;
    int s = __ldg(src + e), d = __ldg(dst + e);
    float w = __expf(lrelu(g_as2[s] + g_ad2[d])) / g_z2[d];
    const float4* hs = (const float4*)(g_h2 + (size_t)s * C2);
    float* od = g_acc2 + (size_t)d * C2;
#pragma unroll
    for (int i = 0; i < C2 / 4; i++) {
        float4 hv = __ldg(hs + i);
        red_add_v4(od + i * 4, hv.x * w, hv.y * w, hv.z * w, hv.w * w);
    }
}

// ---------------- kernel 7: self msg + b2 + log_softmax ---------------------
__global__ void k_final(const float* __restrict__ b2, float* __restrict__ out) {
    int n = blockIdx.x * blockDim.x + threadIdx.x;
    if (n >= N_NODES) return;
    float sw = __expf(lrelu(g_as2[n] + g_ad2[n])) / g_z2[n];
    float v[C2];
    const float4* ac = (const float4*)(g_acc2 + (size_t)n * C2);
    const float4* hh = (const float4*)(g_h2 + (size_t)n * C2);
#pragma unroll
    for (int i = 0; i < C2 / 4; i++) {
        float4 av = ac[i];
        float4 hv = hh[i];
        v[4 * i + 0] = av.x + sw * hv.x + __ldg(b2 + 4 * i + 0);
        v[4 * i + 1] = av.y + sw * hv.y + __ldg(b2 + 4 * i + 1);
        v[4 * i + 2] = av.z + sw * hv.z + __ldg(b2 + 4 * i + 2);
        v[4 * i + 3] = av.w + sw * hv.w + __ldg(b2 + 4 * i + 3);
    }
    float m = v[0];
#pragma unroll
    for (int i = 1; i < C2; i++) m = fmaxf(m, v[i]);
    float s = 0.f;
#pragma unroll
    for (int i = 0; i < C2; i++) s += expf(v[i] - m);
    float l = m + logf(s);
    float4* o = (float4*)(out + (size_t)n * C2);
#pragma unroll
    for (int i = 0; i < C2 / 4; i++)
        o[i] = make_float4(v[4 * i] - l, v[4 * i + 1] - l, v[4 * i + 2] - l, v[4 * i + 3] - l);
}

// ---------------- launch ----------------------------------------------------
extern "C" void kernel_launch(void* const* d_in, const int* in_sizes, int n_in,
                              void* d_out, int out_size) {
    const float* x     = (const float*)d_in[0];
    const int*   ei    = (const int*)d_in[1];
    const float* W1    = (const float*)d_in[2];
    const float* as1   = (const float*)d_in[3];
    const float* ad1   = (const float*)d_in[4];
    const float* b1    = (const float*)d_in[5];
    const float* W2    = (const float*)d_in[6];
    const float* as2   = (const float*)d_in[7];
    const float* ad2   = (const float*)d_in[8];
    const float* b2    = (const float*)d_in[9];
    float* out = (float*)d_out;

    int E = in_sizes[1] / 2;           // edge_index is [2, E] int32
    const int* src = ei;
    const int* dst = ei + E;

    void *acc1p, *acc2p;
    cudaGetSymbolAddress(&acc1p, g_acc1);
    cudaGetSymbolAddress(&acc2p, g_acc2);
    cudaMemsetAsync(acc1p, 0, sizeof(float) * (size_t)N_NODES * C1);
    cudaMemsetAsync(acc2p, 0, sizeof(float) * (size_t)N_NODES * C2);

    int nb = (N_NODES + 127) / 128;
    int eb = (E + 255) / 256;

    k_gemm1<<<nb, 128>>>(x, W1, as1, ad1);
    k_edge_z1<<<eb, 256>>>(src, dst, E);
    k_edge_msg1<<<eb, 256>>>(src, dst, E);
    k_node2<<<nb, 128>>>(b1, W2, as2, ad2);
    k_edge_z2<<<eb, 256>>>(src, dst, E);
    k_edge_msg2<<<eb, 256>>>(src, dst, E);
    k_final<<<(N_NODES + 255) / 256, 256>>>(b2, out);
}